// round 8
// baseline (speedup 1.0000x reference)
#include <cuda_runtime.h>
#include <stdint.h>
#include <stddef.h>

// Problem constants
#define BB 8
#define CC 64
#define MM 4
#define NN 400
#define TT 24
#define QQ 8
#define PP (MM*NN*TT)        // 38400 columns per batch
#define BNM (BB*NN*MM)       // 12800
#define MASK_NUM 1280        // int(12800*0.1)

typedef unsigned long long ull;

// -------- device scratch (no allocations allowed) --------
__device__ float g_w[BNM];          // w = 1 - sim, flattened (b,n,m)
__device__ float g_levels[25600];   // associative-scan level storage
__device__ float g_scans[25600];    // associative-scan results per level
__device__ int   g_midx[MASK_NUM];  // sampled indices
__device__ float g_Tp[CC*TT];
__device__ float g_Sp[CC*NN];
__device__ float g_Mp[CC*MM];       // includes proj_b folded in

// ============================================================
// forced 4-byte global accesses (no vector merging, L1-cacheable)
// ============================================================
__device__ __forceinline__ float ldg32(const float* p) {
    float v; asm volatile("ld.global.f32 %0, [%1];" : "=f"(v) : "l"(p)); return v;
}
__device__ __forceinline__ void stg32(float* p, float v) {
    asm volatile("st.global.f32 [%0], %1;" :: "l"(p), "f"(v));
}

// ============================================================
// XLA:CPU exp (GenerateVF32Exp / Cephes pexp, UNFUSED mul+add)
// ============================================================
__device__ __forceinline__ float xla_exp(float input) {
    float x = fminf(input, 88.3762626647950f);
    x = fmaxf(x, -88.3762626647949f);
    float fx = __fadd_rn(__fmul_rn(x, 1.44269504088896341f), 0.5f);
    fx = floorf(fx);
    float tmp = __fmul_rn(fx, 0.693359375f);
    float z   = __fmul_rn(fx, -2.12194440e-4f);
    x = __fsub_rn(x, tmp);
    x = __fsub_rn(x, z);
    z = __fmul_rn(x, x);
    float y = 1.9875691500E-4f;
    y = __fadd_rn(__fmul_rn(y, x), 1.3981999507E-3f);
    y = __fadd_rn(__fmul_rn(y, x), 8.3334519073E-3f);
    y = __fadd_rn(__fmul_rn(y, x), 4.1665795894E-2f);
    y = __fadd_rn(__fmul_rn(y, x), 1.6666665459E-1f);
    y = __fadd_rn(__fmul_rn(y, x), 5.0000001201E-1f);
    y = __fadd_rn(__fmul_rn(y, z), x);
    y = __fadd_rn(y, 1.0f);
    int emm0 = (int)fx;
    emm0 = (emm0 + 0x7f) << 23;
    return __fmul_rn(y, __int_as_float(emm0));
}

// ============================================================
// packed f32x2 helpers (sm_100+)
// ============================================================
__device__ __forceinline__ void ffma2(ull& d, ull a, ull b) {
    asm("fma.rn.f32x2 %0, %1, %2, %0;" : "+l"(d) : "l"(a), "l"(b));
}
__device__ __forceinline__ ull dup2(float x) {
    ull r; asm("mov.b64 %0, {%1,%1};" : "=l"(r) : "f"(x)); return r;
}
__device__ __forceinline__ float2 u2f(ull v) {
    float2 r; asm("mov.b64 {%0,%1}, %2;" : "=f"(r.x), "=f"(r.y) : "l"(v)); return r;
}

// ============================================================
// threefry2x32-20, key = PRNGKey(42) = (0, 42)
// ============================================================
__device__ __forceinline__ uint32_t rotl32(uint32_t x, int r) {
    return (x << r) | (x >> (32 - r));
}
__device__ void threefry2x32(uint32_t c0, uint32_t c1, uint32_t& o0, uint32_t& o1) {
    const uint32_t k0 = 0u, k1 = 42u;
    uint32_t ks[3] = {k0, k1, 0x1BD11BDAu ^ k0 ^ k1};
    uint32_t x0 = c0 + ks[0];
    uint32_t x1 = c1 + ks[1];
    const int rotA[4] = {13,15,26,6};
    const int rotB[4] = {17,29,16,24};
#pragma unroll
    for (int i = 0; i < 5; i++) {
#pragma unroll
        for (int j = 0; j < 4; j++) {
            int r = (i & 1) ? rotB[j] : rotA[j];
            x0 += x1;
            x1 = rotl32(x1, r);
            x1 ^= x0;
        }
        x0 += ks[(i + 1) % 3];
        x1 += ks[(i + 2) % 3] + (uint32_t)(i + 1);
    }
    o0 = x0; o1 = x1;
}

// ============================================================
// k_pre: blocks 0..199 -> sim/w (coalesced); blocks 200..306 -> Tp/Sp/Mp
// ============================================================
__global__ void __launch_bounds__(256) k_pre(
    const float* __restrict__ rep,
    const float* __restrict__ att_w,
    const float* __restrict__ att_b,
    const float* __restrict__ temb,
    const float* __restrict__ semb,
    const float* __restrict__ memb,
    const float* __restrict__ proj_w,
    const float* __restrict__ proj_b)
{
    const int bid = blockIdx.x;
    const int tid = threadIdx.x;

    if (bid >= 200) {   // ---- embedding projections ----
        const int idx = (bid - 200) * 256 + tid;
        const int total = CC * (TT + NN + MM);
        if (idx >= total) return;
        const int o = idx / (TT + NN + MM);
        const int j = idx % (TT + NN + MM);
        const float* w2 = proj_w + o*2*CC + CC;   // W2[o][c] = proj_w[o,64+c]
        float acc = 0.f;
        if (j < TT) {
#pragma unroll 8
            for (int c = 0; c < CC; c++) acc = fmaf(w2[c], temb[c*TT + j], acc);
            g_Tp[o*TT + j] = acc;
        } else if (j < TT + NN) {
            const int n = j - TT;
#pragma unroll 8
            for (int c = 0; c < CC; c++) acc = fmaf(w2[c], semb[c*NN + n], acc);
            g_Sp[o*NN + n] = acc;
        } else {
            const int m = j - TT - NN;
#pragma unroll 8
            for (int c = 0; c < CC; c++) acc = fmaf(w2[c], memb[c*MM + m], acc);
            g_Mp[o*MM + m] = acc + proj_b[o];
        }
        return;
    }

    // ---- sim: block = (b, 16 n's); coalesced tile staging ----
    __shared__ float tile[CC*MM][17];   // [e=c*4+m][j]
    __shared__ float aw[QQ*CC];
    __shared__ float pm_s[QQ][16][4];
    const int b  = bid / 25;
    const int n0 = (bid % 25) * 16;

    for (int i = tid; i < QQ*CC; i += 256) aw[i] = att_w[i];
    const float* repb = rep + (size_t)b * CC * MM * NN + n0;
    for (int idx = tid; idx < CC*MM*16; idx += 256) {
        int e = idx >> 4, j = idx & 15;
        tile[e][j] = repb[(size_t)e * NN + j];
    }
    __syncthreads();

    if (tid < 128) {
        const int q = tid >> 4, j = tid & 15;
        float A[4];
#pragma unroll
        for (int m = 0; m < 4; m++) {
            float acc = 0.f;   // ascending-c single fma chain (frozen order)
#pragma unroll 8
            for (int c = 0; c < CC; c++)
                acc = fmaf(tile[c*4 + m][j], aw[q*CC + c], acc);
            A[m] = __fadd_rn(acc, att_b[q]);
        }
        float mx = fmaxf(fmaxf(fmaxf(A[0], A[1]), A[2]), A[3]);
        float e[4];
#pragma unroll
        for (int m = 0; m < 4; m++) e[m] = xla_exp(__fsub_rn(A[m], mx));
        float s = __fadd_rn(__fadd_rn(__fadd_rn(e[0], e[1]), e[2]), e[3]);
#pragma unroll
        for (int m = 0; m < 4; m++) pm_s[q][j][m] = __fdiv_rn(e[m], s);
    }
    __syncthreads();

    if (tid < 64) {
        const int j = tid >> 2, m = tid & 3;
        float sumq = 0.f;
#pragma unroll
        for (int q = 0; q < 8; q++) sumq = __fadd_rn(sumq, pm_s[q][j][m]);
        float sim = __fmul_rn(sumq, 0.125f);
        g_w[(b*NN + n0 + j)*MM + m] = __fsub_rn(1.0f, sim);
    }
}

// ============================================================
// mask pipeline (block 0 of merged kernel, 256 threads)
// ALL float ops bit-identical to the passing R6 version.
// ============================================================
__device__ void mask_work() {
    const int tid = threadIdx.x;
    __shared__ float S_sh;
    __shared__ float lane_sums[4];
    const int sizes[14] = {12800,6400,3200,1600,800,400,200,100,50,25,12,6,3,1};
    int offs[14];
    { int o = 0; for (int k = 0; k < 14; k++) { offs[k] = o; o += sizes[k]; } }

    // ---- S = sum(w): XLA:CPU EmitVectorizedReduce, NEON 4-lane ----
    if (tid < 4) {
        float a = 0.f;
#pragma unroll 8
        for (int j = 0; j < BNM/4; j++)
            a = __fadd_rn(a, ldg32(&g_w[4*j + tid]));
        lane_sums[tid] = a;
    }
    __syncthreads();
    if (tid == 0) {
        float lo = __fadd_rn(lane_sums[0], lane_sums[2]);
        float hi = __fadd_rn(lane_sums[1], lane_sums[3]);
        S_sh = __fadd_rn(lo, hi);
    }
    __syncthreads();
    const float S = S_sh;

    // ---- level 0: p = w / S ----
    for (int i = tid; i < BNM; i += 256)
        stg32(&g_levels[i], __fdiv_rn(ldg32(&g_w[i]), S));
    __syncthreads();

    // ---- down-sweep ----
    for (int k = 0; k < 13; k++) {
        const int so = offs[k], dofs = offs[k+1];
        const int nk1 = sizes[k+1];
        for (int i = tid; i < nk1; i += 256) {
            float a  = ldg32(&g_levels[so + 2*i]);
            float b2 = ldg32(&g_levels[so + 2*i + 1]);
            stg32(&g_levels[dofs + i], __fadd_rn(a, b2));
        }
        __syncthreads();
    }
    // ---- up-sweep: jax associative_scan interleave ----
    if (tid == 0) stg32(&g_scans[offs[13]], ldg32(&g_levels[offs[13]]));
    __syncthreads();
    for (int k = 12; k >= 0; k--) {
        const int lo_ = offs[k], ho = offs[k+1];
        const int nk = sizes[k], nk1 = sizes[k+1];
        if (tid == 0) stg32(&g_scans[lo_], ldg32(&g_levels[lo_]));
        for (int i = tid; i < nk1; i += 256) {
            float sv = ldg32(&g_scans[ho + i]);
            stg32(&g_scans[lo_ + 2*i + 1], sv);
            if (2*i + 2 < nk)
                stg32(&g_scans[lo_ + 2*i + 2],
                      __fadd_rn(sv, ldg32(&g_levels[lo_ + 2*i + 2])));
        }
        __syncthreads();
    }
    const float plast = ldg32(&g_scans[BNM - 1]);

    // ---- sample 1280 indices (jax searchsorted method='scan'), 5-wide ILP ----
    float rr[5]; int lo5[5], hi5[5];
#pragma unroll
    for (int s = 0; s < 5; s++) {
        int k = tid + s*256;
        uint32_t o0, o1;
        threefry2x32(0u, (uint32_t)k, o0, o1);   // partitionable mode
        uint32_t bits = o0 ^ o1;
        float u = __fsub_rn(__uint_as_float((bits >> 9) | 0x3f800000u), 1.0f);
        rr[s] = __fmul_rn(plast, __fsub_rn(1.0f, u));
        lo5[s] = 0; hi5[s] = BNM;
    }
#pragma unroll
    for (int it = 0; it < 14; it++) {            // ceil(log2(12801)) = 14
#pragma unroll
        for (int s = 0; s < 5; s++) {
            int mid = (lo5[s] + hi5[s]) >> 1;
            float v = g_scans[mid];
            if (rr[s] <= v) hi5[s] = mid; else lo5[s] = mid;
        }
    }
#pragma unroll
    for (int s = 0; s < 5; s++) g_midx[tid + s*256] = hi5[s];
}

// ============================================================
// Merged kernel: block 0 = mask pipeline; blocks 1..2400 = GEMM
// out[b,o,p] = relu( sum_c W1[o,c]*x[b,c,p] + Tp[o,t]+Sp[o,n]+Mp[o,m] )
// acc pairs over p: acc[o][pp] = (out[o][2pp], out[o][2pp+1])
// X read as natural (x0,x1) pairs (LDS.128); W duplicated (w,w) in smem.
// dynamic smem: Wd 64 rows x 66 ull (33792 B) + Xsh 32x32 float4 (16384 B)
// ============================================================
#define WROW 66
#define SMEM_BYTES (CC*WROW*8 + 32*32*16)

__global__ void __launch_bounds__(256) k_merged(const float* __restrict__ x,
                                                const float* __restrict__ proj_w,
                                                float* __restrict__ out) {
    extern __shared__ __align__(16) char dsm[];
    ull*    Wd  = (ull*)dsm;                       // [c][o] duplicated, row WROW
    float4* Xsh = (float4*)(dsm + CC*WROW*8);      // [cc][p4]

    if (blockIdx.x == 0) { mask_work(); return; }

    const int g  = blockIdx.x - 1;
    const int b  = g / 300;
    const int p0 = (g % 300) * 128;
    const int tid = threadIdx.x;
    const int to = tid >> 5;            // 0..7 -> o base = to*8
    const int tp = tid & 31;            // 0..31 -> p = p0 + tp*4 + pj

    // stage W duplicated: Wd[c*WROW + o] = (w,w),  w = proj_w[o*128 + c]
    for (int i = tid; i < CC*CC; i += 256) {
        int o = i >> 6, c = i & 63;
        Wd[c*WROW + o] = dup2(proj_w[o*2*CC + c]);
    }

    ull acc[8][2];
#pragma unroll
    for (int oo = 0; oo < 8; oo++) { acc[oo][0] = 0ull; acc[oo][1] = 0ull; }

    const size_t xbase = (size_t)b * CC * PP + p0;
    const ulonglong2* Xull = (const ulonglong2*)Xsh;

#pragma unroll
    for (int ch = 0; ch < 2; ch++) {
        __syncthreads();   // ch0: before Xsh write; ch1: Xsh reads done
#pragma unroll
        for (int it = 0; it < 4; it++) {
            int idx = it*256 + tid;
            int cc = idx >> 5, p4 = idx & 31;
            Xsh[cc*32 + p4] = *(const float4*)(x + xbase + (size_t)(ch*32 + cc)*PP + p4*4);
        }
        __syncthreads();

#pragma unroll 8
        for (int cc = 0; cc < 32; cc++) {
            const int c = ch*32 + cc;
            ulonglong2 xp = Xull[cc*32 + tp];      // (x0,x1),(x2,x3)
            const ull* wrow = Wd + c*WROW + to*8;  // 16B-aligned (528c%16==0)
            ulonglong2 w01 = *(const ulonglong2*)(wrow);
            ulonglong2 w23 = *(const ulonglong2*)(wrow + 2);
            ulonglong2 w45 = *(const ulonglong2*)(wrow + 4);
            ulonglong2 w67 = *(const ulonglong2*)(wrow + 6);
            ffma2(acc[0][0], w01.x, xp.x); ffma2(acc[0][1], w01.x, xp.y);
            ffma2(acc[1][0], w01.y, xp.x); ffma2(acc[1][1], w01.y, xp.y);
            ffma2(acc[2][0], w23.x, xp.x); ffma2(acc[2][1], w23.x, xp.y);
            ffma2(acc[3][0], w23.y, xp.x); ffma2(acc[3][1], w23.y, xp.y);
            ffma2(acc[4][0], w45.x, xp.x); ffma2(acc[4][1], w45.x, xp.y);
            ffma2(acc[5][0], w45.y, xp.x); ffma2(acc[5][1], w45.y, xp.y);
            ffma2(acc[6][0], w67.x, xp.x); ffma2(acc[6][1], w67.x, xp.y);
            ffma2(acc[7][0], w67.y, xp.x); ffma2(acc[7][1], w67.y, xp.y);
        }
    }

    // ---- epilogue ----
    const int m = p0 / 9600;
    const int obase = to*8;
    int tv[4], nv[4];
#pragma unroll
    for (int pj = 0; pj < 4; pj++) {
        int p = p0 + tp*4 + pj;
        tv[pj] = p % 24;
        nv[pj] = (p / 24) % 400;
    }
#pragma unroll
    for (int oo = 0; oo < 8; oo++) {
        const int o = obase + oo;
        float mpv = g_Mp[o*MM + m];
        float2 a01 = u2f(acc[oo][0]);
        float2 a23 = u2f(acc[oo][1]);
        float av[4] = {a01.x, a01.y, a23.x, a23.y};
        float4 v;
        v.x = fmaxf(av[0] + g_Tp[o*TT + tv[0]] + g_Sp[o*NN + nv[0]] + mpv, 0.f);
        v.y = fmaxf(av[1] + g_Tp[o*TT + tv[1]] + g_Sp[o*NN + nv[1]] + mpv, 0.f);
        v.z = fmaxf(av[2] + g_Tp[o*TT + tv[2]] + g_Sp[o*NN + nv[2]] + mpv, 0.f);
        v.w = fmaxf(av[3] + g_Tp[o*TT + tv[3]] + g_Sp[o*NN + nv[3]] + mpv, 0.f);
        *(float4*)(out + (size_t)(b*CC + o)*PP + p0 + tp*4) = v;
    }
}

// ============================================================
// k_fix: overwrite the 1280 masked (b,n,m) slices with relu(emb only)
// ============================================================
__global__ void __launch_bounds__(256) k_fix(float* __restrict__ out) {
    const int idx = g_midx[blockIdx.x];
    const int b = idx / (NN*MM);
    const int rr = idx % (NN*MM);
    const int n = rr >> 2;
    const int m = rr & 3;
    const int tid = threadIdx.x;
#pragma unroll
    for (int j = 0; j < 6; j++) {
        int i = j*256 + tid;           // i in [0,1536): o = i/24, t = i%24
        int o = i / 24;
        int t = i % 24;
        float v = g_Tp[o*TT + t] + g_Sp[o*NN + n] + g_Mp[o*MM + m];
        out[((size_t)(b*CC + o)*MM + m)*NN*TT + n*TT + t] = fmaxf(v, 0.0f);
    }
}

// ============================================================
extern "C" void kernel_launch(void* const* d_in, const int* in_sizes, int n_in,
                              void* d_out, int out_size) {
    const float* x      = (const float*)d_in[0];
    const float* rep    = (const float*)d_in[1];
    const float* att_w  = (const float*)d_in[2];
    const float* att_b  = (const float*)d_in[3];
    const float* temb   = (const float*)d_in[4];
    const float* semb   = (const float*)d_in[5];
    const float* memb   = (const float*)d_in[6];
    const float* proj_w = (const float*)d_in[7];
    const float* proj_b = (const float*)d_in[8];
    float* out = (float*)d_out;

    cudaFuncSetAttribute(k_merged, cudaFuncAttributeMaxDynamicSharedMemorySize,
                         SMEM_BYTES);

    k_pre<<<307, 256>>>(rep, att_w, att_b, temb, semb, memb, proj_w, proj_b);
    k_merged<<<2401, 256, SMEM_BYTES>>>(x, proj_w, out);
    k_fix<<<MASK_NUM, 256>>>(out);
}